// round 7
// baseline (speedup 1.0000x reference)
#include <cuda_runtime.h>
#include <cstdint>

// Problem constants
#define NB   16
#define NL   128
#define NE   300
#define NH   512
#define NT   9
#define NBIOE 64
#define NREL 128
#define NR   50

// ---------------- scratch layout (floats) ----------------
#define EMB_OFF    0            // 2048*300
#define BSUM_OFF   1228800      // 2*2048
#define XP_OFF     1232896      // 2 * 2048*2048
#define HS_OFF     9621504      // 2 * 128*16*512
#define EMI_OFF    12783616     // 2048*9
#define OC_OFF     12802048     // 2048*576
#define U_OFF      13981696     // 2048*128
#define V_OFF      14243840     // 2048*128
#define U1_OFF     14505984     // 2048*128
#define V2_OFF     14768128     // 2048*128
#define MASKF_OFF  15030272     // 2048
#define SCRATCH_SZ 15032320

__device__ __align__(16) float g_scratch[SCRATCH_SZ];
__device__ double g_sel_sum;
__device__ int    g_mask_count;
__device__ float  g_crf_loss;
__device__ unsigned g_arrive;
__device__ unsigned g_release;

__device__ __forceinline__ float sigm(float x) { return 1.f / (1.f + expf(-x)); }

#define FMA_F32X2(d, a, b) \
    asm("fma.rn.f32x2 %0, %1, %2, %0;" : "+l"(d) : "l"(a), "l"(b))

// ---------------- zero accumulators ----------------
__global__ void zero_kernel() {
    g_sel_sum = 0.0;
    g_mask_count = 0;
    g_crf_loss = 0.f;
    g_arrive = 0u;
    g_release = 0u;
}

// ---------------- embedding gather + mask ----------------
__global__ void embed_kernel(const int* __restrict__ tokens,
                             const float* __restrict__ wemb) {
    int idx = blockIdx.x * blockDim.x + threadIdx.x;   // < 2048*300
    int bl = idx / NE;
    int e  = idx - bl * NE;
    int tok = tokens[bl];
    g_scratch[EMB_OFF + idx] = wemb[(size_t)tok * NE + e];
    if (e == 0) {
        g_scratch[MASKF_OFF + bl] = (tok != 0) ? 1.f : 0.f;
        if (tok != 0) atomicAdd(&g_mask_count, 1);
    }
}

// ---------------- combined biases ----------------
__global__ void bsum_kernel(const float* bif, const float* bhf,
                            const float* bib, const float* bhb) {
    int idx = blockIdx.x * blockDim.x + threadIdx.x;   // < 4096
    int d = idx >> 11, g = idx & 2047;
    g_scratch[BSUM_OFF + idx] = d ? (bib[g] + bhb[g]) : (bif[g] + bhf[g]);
}

// ---------------- fused xproj GEMM: both directions, one pass over emb -------
// C[2048, 4096] = emb[2048, 300] @ [w_ih_f ; w_ih_b]^T + bsum
// Backward half written with l -> 127-l (replaces the emb-reverse pass).
// Tiles: 128 rows x 64 cols, 256 threads, thread tile 8x4, k-tile 16.
#define KTILE 16
__global__ __launch_bounds__(256) void xproj_gemm(
    const float* __restrict__ wf, const float* __restrict__ wb)
{
    __shared__ float As[KTILE][132];   // transposed: As[k][m]
    __shared__ float Bs[KTILE][68];    // transposed: Bs[k][n]
    int tid = threadIdx.x;
    int tx = tid & 15, ty = tid >> 4;
    int rowBase = blockIdx.y * 128;    // one full batch
    int colBase = blockIdx.x * 64;
    int dir = colBase >> 11;
    const float* Bmat = dir ? wb : wf;
    int gcol0 = colBase & 2047;

    float acc[8][4];
#pragma unroll
    for (int i = 0; i < 8; i++)
#pragma unroll
        for (int j = 0; j < 4; j++) acc[i][j] = 0.f;

    for (int k0 = 0; k0 < NE; k0 += KTILE) {
        // load A tile (128 x 16), transpose into As[k][m]
#pragma unroll
        for (int i = 0; i < 2; i++) {
            int f = tid + i * 256;
            int r = f >> 2, kq = f & 3;
            int gk = k0 + kq * 4;
            float4 v = make_float4(0.f, 0.f, 0.f, 0.f);
            if (gk < NE)
                v = *reinterpret_cast<const float4*>(
                        &g_scratch[EMB_OFF + (size_t)(rowBase + r) * NE + gk]);
            As[kq * 4 + 0][r] = v.x;
            As[kq * 4 + 1][r] = v.y;
            As[kq * 4 + 2][r] = v.z;
            As[kq * 4 + 3][r] = v.w;
        }
        // load B tile (64 x 16), transpose into Bs[k][n]
        {
            int n = tid >> 2, kq = tid & 3;
            int gk = k0 + kq * 4;
            float4 v = make_float4(0.f, 0.f, 0.f, 0.f);
            if (gk < NE)
                v = *reinterpret_cast<const float4*>(
                        &Bmat[(size_t)(gcol0 + n) * NE + gk]);
            Bs[kq * 4 + 0][n] = v.x;
            Bs[kq * 4 + 1][n] = v.y;
            Bs[kq * 4 + 2][n] = v.z;
            Bs[kq * 4 + 3][n] = v.w;
        }
        __syncthreads();
#pragma unroll
        for (int k = 0; k < KTILE; k++) {
            float4 a0 = *reinterpret_cast<const float4*>(&As[k][ty * 8]);
            float4 a1 = *reinterpret_cast<const float4*>(&As[k][ty * 8 + 4]);
            float4 bq = *reinterpret_cast<const float4*>(&Bs[k][tx * 4]);
            acc[0][0] += a0.x * bq.x; acc[0][1] += a0.x * bq.y; acc[0][2] += a0.x * bq.z; acc[0][3] += a0.x * bq.w;
            acc[1][0] += a0.y * bq.x; acc[1][1] += a0.y * bq.y; acc[1][2] += a0.y * bq.z; acc[1][3] += a0.y * bq.w;
            acc[2][0] += a0.z * bq.x; acc[2][1] += a0.z * bq.y; acc[2][2] += a0.z * bq.z; acc[2][3] += a0.z * bq.w;
            acc[3][0] += a0.w * bq.x; acc[3][1] += a0.w * bq.y; acc[3][2] += a0.w * bq.z; acc[3][3] += a0.w * bq.w;
            acc[4][0] += a1.x * bq.x; acc[4][1] += a1.x * bq.y; acc[4][2] += a1.x * bq.z; acc[4][3] += a1.x * bq.w;
            acc[5][0] += a1.y * bq.x; acc[5][1] += a1.y * bq.y; acc[5][2] += a1.y * bq.z; acc[5][3] += a1.y * bq.w;
            acc[6][0] += a1.z * bq.x; acc[6][1] += a1.z * bq.y; acc[6][2] += a1.z * bq.z; acc[6][3] += a1.z * bq.w;
            acc[7][0] += a1.w * bq.x; acc[7][1] += a1.w * bq.y; acc[7][2] += a1.w * bq.z; acc[7][3] += a1.w * bq.w;
        }
        __syncthreads();
    }

    float4 bias = *reinterpret_cast<const float4*>(
        &g_scratch[BSUM_OFF + dir * 2048 + gcol0 + tx * 4]);
    int b = rowBase >> 7;
#pragma unroll
    for (int i = 0; i < 8; i++) {
        int rw = ty * 8 + i;
        int lo = dir ? (127 - rw) : rw;
        float4 v = make_float4(acc[i][0] + bias.x, acc[i][1] + bias.y,
                               acc[i][2] + bias.z, acc[i][3] + bias.w);
        *reinterpret_cast<float4*>(
            &g_scratch[XP_OFF + (size_t)dir * 4194304
                       + (size_t)(b * 128 + lo) * 2048 + gcol0 + tx * 4]) = v;
    }
}

// ---------------- generic NT SGEMM (small selection GEMMs) -------------------
__global__ __launch_bounds__(256) void sgemm_nt(
    int aOff, int lda, const float* __restrict__ Bm, int ldb,
    int cOff, int N, int K,
    const float* __restrict__ biasExt, int relu)
{
    __shared__ float As[64][33];
    __shared__ float Bs[64][33];
    int tid = threadIdx.x;
    int tx = tid & 15, ty = tid >> 4;
    int rowBase = blockIdx.y * 64;
    int colBase = blockIdx.x * 64;
    const float* A = g_scratch + aOff;

    float acc[4][4];
#pragma unroll
    for (int i = 0; i < 4; i++)
#pragma unroll
        for (int j = 0; j < 4; j++) acc[i][j] = 0.f;

    for (int k0 = 0; k0 < K; k0 += 32) {
#pragma unroll
        for (int i = 0; i < 8; i++) {
            int p = tid + i * 256;
            int r = p >> 5, c = p & 31;
            int gk = k0 + c;
            As[r][c] = (gk < K) ? A[(size_t)(rowBase + r) * lda + gk] : 0.f;
            Bs[r][c] = (gk < K) ? Bm[(size_t)(colBase + r) * ldb + gk] : 0.f;
        }
        __syncthreads();
#pragma unroll
        for (int k = 0; k < 32; k++) {
            float a0 = As[ty * 4 + 0][k], a1 = As[ty * 4 + 1][k];
            float a2 = As[ty * 4 + 2][k], a3 = As[ty * 4 + 3][k];
            float b0 = Bs[tx * 4 + 0][k], b1 = Bs[tx * 4 + 1][k];
            float b2 = Bs[tx * 4 + 2][k], b3 = Bs[tx * 4 + 3][k];
            acc[0][0] += a0 * b0; acc[0][1] += a0 * b1; acc[0][2] += a0 * b2; acc[0][3] += a0 * b3;
            acc[1][0] += a1 * b0; acc[1][1] += a1 * b1; acc[1][2] += a1 * b2; acc[1][3] += a1 * b3;
            acc[2][0] += a2 * b0; acc[2][1] += a2 * b1; acc[2][2] += a2 * b2; acc[2][3] += a2 * b3;
            acc[3][0] += a3 * b0; acc[3][1] += a3 * b1; acc[3][2] += a3 * b2; acc[3][3] += a3 * b3;
        }
        __syncthreads();
    }

    float* C = g_scratch + cOff;
#pragma unroll
    for (int i = 0; i < 4; i++) {
        int row = rowBase + ty * 4 + i;
#pragma unroll
        for (int jn = 0; jn < 4; jn++) {
            int col = colBase + tx * 4 + jn;
            float v = acc[i][jn];
            if (biasExt) v += biasExt[col];
            if (relu) v = fmaxf(v, 0.f);
            C[(size_t)row * N + col] = v;
        }
    }
}

// ---------------- persistent BiLSTM: all 128 timesteps in one kernel ---------
// Grid: 128 blocks = dir(2) x slice(64). Block owns 8 j's x 4 gates = 32 gate
// rows; W_hh slice register-resident. k-split (ks) lives in the lane index so
// the 8 partials per (gate-row, batch) reduce via 3 shfl_xor — no partials
// smem, one syncthreads per step before fuse.
// smem: 32KB (h) + 2KB (gates) dynamic + 512B static.
__global__ __launch_bounds__(256, 1) void lstm_persist(
    const float* __restrict__ whhf, const float* __restrict__ whhb)
{
    int bx  = blockIdx.x;
    int dir = bx & 1;
    int s   = bx >> 1;          // 0..63
    int j0  = s * 8;
    const float* whh = dir ? whhb : whhf;

    extern __shared__ float dsh[];
    float4* h4 = (float4*)dsh;             // 2048 float4 = 32KB: h_prev[16][512]
    float*  sg = dsh + 8192;               // [4 gates][16 b][8 jj] = 512 floats
    __shared__ float sc[128];              // cell state (b, jj)

    int tid = threadIdx.x;
    int w   = tid >> 5, l = tid & 31;
    int row = w * 4 + (l >> 3);            // 0..31: block's gate row
    int ks  = l & 7;                       // k-split (64 k each), lane-level
    int g   = row >> 3, jj = row & 7;
    int gr  = g * 512 + j0 + jj;           // global gate row [0,2048)

    // preload W slice: W[gr][ks*64 .. ks*64+63] as f32x2 pairs
    unsigned long long wreg[32];
    {
        const ulonglong2* wsrc =
            reinterpret_cast<const ulonglong2*>(whh + (size_t)gr * 512 + ks * 64);
#pragma unroll
        for (int kk = 0; kk < 16; kk++) {
            ulonglong2 wv = wsrc[kk];
            wreg[2 * kk] = wv.x;
            wreg[2 * kk + 1] = wv.y;
        }
    }
    if (tid < 128) sc[tid] = 0.f;

    for (int t = 0; t < NL; t++) {
        // ---- load h_prev into smem ----
        if (t == 0) {
            float4 z = make_float4(0.f, 0.f, 0.f, 0.f);
            for (int p = tid; p < 2048; p += 256) h4[p] = z;
        } else {
            const float4* hsrc = reinterpret_cast<const float4*>(
                g_scratch + HS_OFF + (size_t)dir * 1048576 + (size_t)(t - 1) * 8192);
            for (int p = tid; p < 2048; p += 256) h4[p] = hsrc[p];
        }
        __syncthreads();

        // ---- matvec, shfl-reduce over ks, scatter gate values ----
#pragma unroll 1
        for (int b = 0; b < 16; b++) {
            const ulonglong2* hb =
                reinterpret_cast<const ulonglong2*>(h4 + b * 128 + ks * 16);
            unsigned long long acc2 = 0ull;
#pragma unroll
            for (int kk = 0; kk < 16; kk++) {
                ulonglong2 h2 = hb[kk];
                FMA_F32X2(acc2, wreg[2 * kk], h2.x);
                FMA_F32X2(acc2, wreg[2 * kk + 1], h2.y);
            }
            float2 af = *reinterpret_cast<float2*>(&acc2);
            float val = af.x + af.y;
            val += __shfl_xor_sync(0xFFFFFFFFu, val, 1);
            val += __shfl_xor_sync(0xFFFFFFFFu, val, 2);
            val += __shfl_xor_sync(0xFFFFFFFFu, val, 4);
            if (ks == (b & 7)) sg[g * 128 + b * 8 + jj] = val;
        }
        __syncthreads();

        // ---- gate fuse + cell update (128 threads: b x jj) ----
        if (tid < 128) {
            int b = tid >> 3, j2 = tid & 7;
            const float* xp = g_scratch + XP_OFF + (size_t)dir * 4194304
                              + (size_t)(b * NL + t) * 2048;
            int j = j0 + j2;
            float iv = sg[0 * 128 + b * 8 + j2] + xp[j];
            float fv = sg[1 * 128 + b * 8 + j2] + xp[512 + j];
            float gv = sg[2 * 128 + b * 8 + j2] + xp[1024 + j];
            float ov = sg[3 * 128 + b * 8 + j2] + xp[1536 + j];
            float cold = sc[tid];
            float cnew = sigm(fv) * cold + sigm(iv) * tanhf(gv);
            float hnew = sigm(ov) * tanhf(cnew);
            sc[tid] = cnew;
            g_scratch[HS_OFF + (size_t)dir * 1048576 + (size_t)t * 8192
                      + (size_t)b * 512 + j] = hnew;
        }
        __syncthreads();

        // ---- grid barrier (monotonic counters, reset by zero_kernel) ----
        if (tid == 0) {
            __threadfence();
            unsigned a = atomicAdd(&g_arrive, 1u) + 1u;
            unsigned target = (unsigned)(128 * (t + 1));
            if (a == target) {
                atomicExch(&g_release, (unsigned)(t + 1));
            } else {
                while (atomicAdd(&g_release, 0u) < (unsigned)(t + 1)) { }
            }
            __threadfence();
        }
        __syncthreads();
    }
}

// ---------------- oc = concat(0.5*(hf+hb_rev), bio_emb[bio_gold]) ------------
__global__ void oc_kernel(const int* __restrict__ biog, const float* __restrict__ bemb) {
    int idx = blockIdx.x * blockDim.x + threadIdx.x;   // < 2048*576
    int row = idx / 576, k = idx - row * 576;
    float v;
    if (k < 512) {
        int b = row >> 7, ll = row & 127;
        float hf = g_scratch[HS_OFF + (size_t)ll * 8192 + (size_t)b * 512 + k];
        float hb = g_scratch[HS_OFF + 1048576 + (size_t)(NL - 1 - ll) * 8192 + (size_t)b * 512 + k];
        v = 0.5f * (hf + hb);
    } else {
        v = bemb[(size_t)biog[row] * NBIOE + (k - 512)];
    }
    g_scratch[OC_OFF + idx] = v;
}

// ---------------- emission: emi = o @ Ew^T + eb (o = OC[:, :512]) ------------
__global__ void emi_kernel(const float* __restrict__ ew, const float* __restrict__ eb) {
    int idx = blockIdx.x * blockDim.x + threadIdx.x;
    if (idx >= 2048 * NT) return;
    int row = idx / NT, tag = idx - row * NT;
    const float4* o4 = reinterpret_cast<const float4*>(g_scratch + OC_OFF + (size_t)row * 576);
    const float4* w4 = reinterpret_cast<const float4*>(ew + (size_t)tag * 512);
    float s = 0.f;
#pragma unroll 4
    for (int k = 0; k < 128; k++) {
        float4 a = o4[k], b = w4[k];
        s += a.x * b.x + a.y * b.y + a.z * b.z + a.w * b.w;
    }
    g_scratch[EMI_OFF + idx] = s + eb[tag];
}

// ---------------- CRF NLL (tiny; 1 block) ----------------
__global__ void crf_kernel(const int* __restrict__ tokens, const int* __restrict__ tags,
                           const float* __restrict__ trans, const float* __restrict__ startv,
                           const float* __restrict__ endv)
{
    __shared__ float st[81], ss[9], se[9];
    __shared__ float alpha[16][9], nxt[16][9];
    __shared__ float num[16];
    __shared__ int prev[16];
    __shared__ float res[16];
    int tid = threadIdx.x;
    if (tid < 81) st[tid] = trans[tid];
    if (tid < 9) { ss[tid] = startv[tid]; se[tid] = endv[tid]; }
    __syncthreads();
    int b = tid / 9, j = tid - b * 9;
    const float* emi = g_scratch + EMI_OFF;
    if (tid < 144) {
        alpha[b][j] = ss[j] + emi[(size_t)(b * NL) * NT + j];
        if (j == 0) {
            int t0 = tags[b * NL];
            num[b] = ss[t0] + emi[(size_t)(b * NL) * NT + t0];
            prev[b] = t0;
        }
    }
    __syncthreads();
    for (int t = 1; t < NL; t++) {
        int m = 0;
        if (tid < 144) {
            m = (tokens[b * NL + t] != 0);
            float mx = -1e30f;
#pragma unroll
            for (int i = 0; i < 9; i++) mx = fmaxf(mx, alpha[b][i] + st[i * 9 + j]);
            float s = 0.f;
#pragma unroll
            for (int i = 0; i < 9; i++) s += expf(alpha[b][i] + st[i * 9 + j] - mx);
            float nv = mx + logf(s) + emi[(size_t)(b * NL + t) * NT + j];
            nxt[b][j] = m ? nv : alpha[b][j];
        }
        __syncthreads();
        if (tid < 144) {
            alpha[b][j] = nxt[b][j];
            if (j == 0 && m) {
                int tg = tags[b * NL + t];
                num[b] += st[prev[b] * 9 + tg] + emi[(size_t)(b * NL + t) * NT + tg];
                prev[b] = tg;
            }
        }
        __syncthreads();
    }
    if (tid < 16) {
        float nb = num[tid] + se[prev[tid]];
        float mx = -1e30f;
        for (int i2 = 0; i2 < 9; i2++) mx = fmaxf(mx, alpha[tid][i2] + se[i2]);
        float s = 0.f;
        for (int i2 = 0; i2 < 9; i2++) s += expf(alpha[tid][i2] + se[i2] - mx);
        res[tid] = nb - (mx + logf(s));
    }
    __syncthreads();
    if (tid == 0) {
        float tot = 0.f;
        for (int i2 = 0; i2 < 16; i2++) tot += res[i2];
        g_crf_loss = -tot / 16.f;
    }
}

// ---------------- fused selection: uv build + einsum + BCE + masked sum ------
__global__ __launch_bounds__(128) void sel_kernel(const int* __restrict__ gold,
                                                  const float* __restrict__ rel,
                                                  const float* __restrict__ uvb)
{
    __shared__ __align__(16) float srel[NR * NREL];   // 25.6KB
    __shared__ __align__(16) float sv0[NREL], sv1[NREL];
    __shared__ float sred[4];

    int bx = blockIdx.x;
    int b  = bx >> 6;
    int i0 = (bx & 63) << 1;
    int tid = threadIdx.x;

    for (int p = tid; p < NR * NREL; p += 128) srel[p] = rel[p];
    const float* v2 = g_scratch + V2_OFF;
    sv0[tid] = v2[(size_t)(b * NL + i0) * NREL + tid] + uvb[tid];
    sv1[tid] = v2[(size_t)(b * NL + i0 + 1) * NREL + tid] + uvb[tid];
    __syncthreads();

    int j = tid;
    const float4* u1r = reinterpret_cast<const float4*>(g_scratch + U1_OFF + (size_t)(b * NL + j) * NREL);
    const float4* s0_4 = reinterpret_cast<const float4*>(sv0);
    const float4* s1_4 = reinterpret_cast<const float4*>(sv1);
    const float4* rel4 = reinterpret_cast<const float4*>(srel);

    float acc0[NR], acc1[NR];
#pragma unroll
    for (int r = 0; r < NR; r++) { acc0[r] = 0.f; acc1[r] = 0.f; }

#pragma unroll 4
    for (int h4 = 0; h4 < 32; h4++) {
        float4 uu = u1r[h4];
        float4 a = s0_4[h4];
        float4 c = s1_4[h4];
        float x0x = fmaxf(uu.x + a.x, 0.f), x0y = fmaxf(uu.y + a.y, 0.f);
        float x0z = fmaxf(uu.z + a.z, 0.f), x0w = fmaxf(uu.w + a.w, 0.f);
        float x1x = fmaxf(uu.x + c.x, 0.f), x1y = fmaxf(uu.y + c.y, 0.f);
        float x1z = fmaxf(uu.z + c.z, 0.f), x1w = fmaxf(uu.w + c.w, 0.f);
#pragma unroll
        for (int r = 0; r < NR; r++) {
            float4 rv = rel4[r * 32 + h4];
            acc0[r] += x0x * rv.x + x0y * rv.y + x0z * rv.z + x0w * rv.w;
            acc1[r] += x1x * rv.x + x1y * rv.y + x1z * rv.z + x1w * rv.w;
        }
    }

    float mi0 = g_scratch[MASKF_OFF + b * NL + i0];
    float mi1 = g_scratch[MASKF_OFF + b * NL + i0 + 1];
    float mj  = g_scratch[MASKF_OFF + b * NL + j];
    const int* g0 = gold + (size_t)(b * NL + i0) * NR * NL + j;
    const int* g1 = gold + (size_t)(b * NL + i0 + 1) * NR * NL + j;
    float s0 = 0.f, s1 = 0.f;
#pragma unroll
    for (int r = 0; r < NR; r++) {
        float x = acc0[r];
        float gg = (float)g0[(size_t)r * NL];
        s0 += fmaxf(x, 0.f) - x * gg + log1pf(expf(-fabsf(x)));
        x = acc1[r];
        gg = (float)g1[(size_t)r * NL];
        s1 += fmaxf(x, 0.f) - x * gg + log1pf(expf(-fabsf(x)));
    }
    float part = mj * (mi0 * s0 + mi1 * s1);

#pragma unroll
    for (int off = 16; off; off >>= 1) part += __shfl_down_sync(0xFFFFFFFFu, part, off);
    if ((tid & 31) == 0) sred[tid >> 5] = part;
    __syncthreads();
    if (tid == 0) {
        double tot = (double)sred[0] + (double)sred[1] + (double)sred[2] + (double)sred[3];
        atomicAdd(&g_sel_sum, tot);
    }
}

// ---------------- final scalar ----------------
__global__ void final_kernel(float* out) {
    out[0] = g_crf_loss + (float)(g_sel_sum / (double)g_mask_count);
}

// ============================================================================
extern "C" void kernel_launch(void* const* d_in, const int* in_sizes, int n_in,
                              void* d_out, int out_size)
{
    const int*   tokens     = (const int*)d_in[0];
    const int*   bio_gold   = (const int*)d_in[1];
    const int*   sel_gold   = (const int*)d_in[2];
    // d_in[3] = is_train (unused)
    const float* word_emb   = (const float*)d_in[4];
    const float* rel_emb    = (const float*)d_in[5];
    const float* bio_emb    = (const float*)d_in[6];
    const float* w_ih_f     = (const float*)d_in[7];
    const float* w_hh_f     = (const float*)d_in[8];
    const float* b_ih_f     = (const float*)d_in[9];
    const float* b_hh_f     = (const float*)d_in[10];
    const float* w_ih_b     = (const float*)d_in[11];
    const float* w_hh_b     = (const float*)d_in[12];
    const float* b_ih_b     = (const float*)d_in[13];
    const float* b_hh_b     = (const float*)d_in[14];
    const float* emission_w = (const float*)d_in[15];
    const float* emission_b = (const float*)d_in[16];
    const float* sel_u_w    = (const float*)d_in[17];
    const float* sel_u_b    = (const float*)d_in[18];
    const float* sel_v_w    = (const float*)d_in[19];
    const float* sel_v_b    = (const float*)d_in[20];
    const float* sel_uv_w   = (const float*)d_in[21];
    const float* sel_uv_b   = (const float*)d_in[22];
    const float* crf_trans  = (const float*)d_in[23];
    const float* crf_start  = (const float*)d_in[24];
    const float* crf_end    = (const float*)d_in[25];

    zero_kernel<<<1, 1>>>();
    embed_kernel<<<2400, 256>>>(tokens, word_emb);
    bsum_kernel<<<16, 256>>>(b_ih_f, b_hh_f, b_ih_b, b_hh_b);

    // fused input projection for both directions (reads emb once)
    xproj_gemm<<<dim3(64, 16), 256>>>(w_ih_f, w_ih_b);

    // persistent BiLSTM over all timesteps (34KB dynamic smem)
    lstm_persist<<<128, 256, 34816>>>(w_hh_f, w_hh_b);

    oc_kernel<<<4608, 256>>>(bio_gold, bio_emb);
    emi_kernel<<<(2048 * NT + 127) / 128, 128>>>(emission_w, emission_b);
    crf_kernel<<<1, 160>>>(tokens, bio_gold, crf_trans, crf_start, crf_end);

    // u = relu(oc @ sel_u_w^T + b), v likewise (A rows stride 576 in OC)
    sgemm_nt<<<dim3(2, 32), 256>>>(OC_OFF, 576, sel_u_w, 576,
                                   U_OFF, NREL, 576, sel_u_b, 1);
    sgemm_nt<<<dim3(2, 32), 256>>>(OC_OFF, 576, sel_v_w, 576,
                                   V_OFF, NREL, 576, sel_v_b, 1);
    // u1 = u @ w1^T, v2 = v @ w2^T  (w1/w2 = halves of sel_uv_w, ldb=256)
    sgemm_nt<<<dim3(2, 32), 256>>>(U_OFF, NREL, sel_uv_w, 2 * NREL,
                                   U1_OFF, NREL, NREL, nullptr, 0);
    sgemm_nt<<<dim3(2, 32), 256>>>(V_OFF, NREL, sel_uv_w + NREL, 2 * NREL,
                                   V2_OFF, NREL, NREL, nullptr, 0);

    sel_kernel<<<1024, 128>>>(sel_gold, rel_emb, sel_uv_b);
    final_kernel<<<1, 1>>>((float*)d_out);
}

// round 8
// speedup vs baseline: 3.7955x; 3.7955x over previous
#include <cuda_runtime.h>
#include <cstdint>

// Problem constants
#define NB   16
#define NL   128
#define NE   300
#define NH   512
#define NT   9
#define NBIOE 64
#define NREL 128
#define NR   50

// ---------------- scratch layout (floats) ----------------
#define EMB_OFF    0            // 2048*300
#define BSUM_OFF   1228800      // 2*2048
#define XP_OFF     1232896      // 2 * 2048*2048
#define HS_OFF     9621504      // 2 * 128*16*512
#define EMI_OFF    12783616     // 2048*9
#define OC_OFF     12802048     // 2048*576
#define U_OFF      13981696     // 2048*128
#define V_OFF      14243840     // 2048*128
#define U1_OFF     14505984     // 2048*128
#define V2_OFF     14768128     // 2048*128
#define MASKF_OFF  15030272     // 2048
#define SCRATCH_SZ 15032320

__device__ __align__(16) float g_scratch[SCRATCH_SZ];
__device__ double g_sel_sum;
__device__ int    g_mask_count;
__device__ float  g_crf_loss;
__device__ unsigned g_arrive;
__device__ unsigned g_release;

__device__ __forceinline__ float sigm(float x) { return 1.f / (1.f + expf(-x)); }

#define FMA_F32X2(d, a, b) \
    asm("fma.rn.f32x2 %0, %1, %2, %0;" : "+l"(d) : "l"(a), "l"(b))

// ---------------- zero accumulators ----------------
__global__ void zero_kernel() {
    g_sel_sum = 0.0;
    g_mask_count = 0;
    g_crf_loss = 0.f;
    g_arrive = 0u;
    g_release = 0u;
}

// ---------------- embedding gather + mask ----------------
__global__ void embed_kernel(const int* __restrict__ tokens,
                             const float* __restrict__ wemb) {
    int idx = blockIdx.x * blockDim.x + threadIdx.x;   // < 2048*300
    int bl = idx / NE;
    int e  = idx - bl * NE;
    int tok = tokens[bl];
    g_scratch[EMB_OFF + idx] = wemb[(size_t)tok * NE + e];
    if (e == 0) {
        g_scratch[MASKF_OFF + bl] = (tok != 0) ? 1.f : 0.f;
        if (tok != 0) atomicAdd(&g_mask_count, 1);
    }
}

// ---------------- combined biases ----------------
__global__ void bsum_kernel(const float* bif, const float* bhf,
                            const float* bib, const float* bhb) {
    int idx = blockIdx.x * blockDim.x + threadIdx.x;   // < 4096
    int d = idx >> 11, g = idx & 2047;
    g_scratch[BSUM_OFF + idx] = d ? (bib[g] + bhb[g]) : (bif[g] + bhf[g]);
}

// ---------------- fused xproj GEMM: both directions, one pass over emb -------
// C[2048, 4096] = emb[2048, 300] @ [w_ih_f ; w_ih_b]^T + bsum
// Backward half written with l -> 127-l (replaces the emb-reverse pass).
// Tiles: 128 rows x 64 cols, 256 threads, thread tile 8x4, k-tile 16.
#define KTILE 16
__global__ __launch_bounds__(256) void xproj_gemm(
    const float* __restrict__ wf, const float* __restrict__ wb)
{
    __shared__ float As[KTILE][132];   // transposed: As[k][m]
    __shared__ float Bs[KTILE][68];    // transposed: Bs[k][n]
    int tid = threadIdx.x;
    int tx = tid & 15, ty = tid >> 4;
    int rowBase = blockIdx.y * 128;    // one full batch
    int colBase = blockIdx.x * 64;
    int dir = colBase >> 11;
    const float* Bmat = dir ? wb : wf;
    int gcol0 = colBase & 2047;

    float acc[8][4];
#pragma unroll
    for (int i = 0; i < 8; i++)
#pragma unroll
        for (int j = 0; j < 4; j++) acc[i][j] = 0.f;

    for (int k0 = 0; k0 < NE; k0 += KTILE) {
        // load A tile (128 x 16), transpose into As[k][m]
#pragma unroll
        for (int i = 0; i < 2; i++) {
            int f = tid + i * 256;
            int r = f >> 2, kq = f & 3;
            int gk = k0 + kq * 4;
            float4 v = make_float4(0.f, 0.f, 0.f, 0.f);
            if (gk < NE)
                v = *reinterpret_cast<const float4*>(
                        &g_scratch[EMB_OFF + (size_t)(rowBase + r) * NE + gk]);
            As[kq * 4 + 0][r] = v.x;
            As[kq * 4 + 1][r] = v.y;
            As[kq * 4 + 2][r] = v.z;
            As[kq * 4 + 3][r] = v.w;
        }
        // load B tile (64 x 16), transpose into Bs[k][n]
        {
            int n = tid >> 2, kq = tid & 3;
            int gk = k0 + kq * 4;
            float4 v = make_float4(0.f, 0.f, 0.f, 0.f);
            if (gk < NE)
                v = *reinterpret_cast<const float4*>(
                        &Bmat[(size_t)(gcol0 + n) * NE + gk]);
            Bs[kq * 4 + 0][n] = v.x;
            Bs[kq * 4 + 1][n] = v.y;
            Bs[kq * 4 + 2][n] = v.z;
            Bs[kq * 4 + 3][n] = v.w;
        }
        __syncthreads();
#pragma unroll
        for (int k = 0; k < KTILE; k++) {
            float4 a0 = *reinterpret_cast<const float4*>(&As[k][ty * 8]);
            float4 a1 = *reinterpret_cast<const float4*>(&As[k][ty * 8 + 4]);
            float4 bq = *reinterpret_cast<const float4*>(&Bs[k][tx * 4]);
            acc[0][0] += a0.x * bq.x; acc[0][1] += a0.x * bq.y; acc[0][2] += a0.x * bq.z; acc[0][3] += a0.x * bq.w;
            acc[1][0] += a0.y * bq.x; acc[1][1] += a0.y * bq.y; acc[1][2] += a0.y * bq.z; acc[1][3] += a0.y * bq.w;
            acc[2][0] += a0.z * bq.x; acc[2][1] += a0.z * bq.y; acc[2][2] += a0.z * bq.z; acc[2][3] += a0.z * bq.w;
            acc[3][0] += a0.w * bq.x; acc[3][1] += a0.w * bq.y; acc[3][2] += a0.w * bq.z; acc[3][3] += a0.w * bq.w;
            acc[4][0] += a1.x * bq.x; acc[4][1] += a1.x * bq.y; acc[4][2] += a1.x * bq.z; acc[4][3] += a1.x * bq.w;
            acc[5][0] += a1.y * bq.x; acc[5][1] += a1.y * bq.y; acc[5][2] += a1.y * bq.z; acc[5][3] += a1.y * bq.w;
            acc[6][0] += a1.z * bq.x; acc[6][1] += a1.z * bq.y; acc[6][2] += a1.z * bq.z; acc[6][3] += a1.z * bq.w;
            acc[7][0] += a1.w * bq.x; acc[7][1] += a1.w * bq.y; acc[7][2] += a1.w * bq.z; acc[7][3] += a1.w * bq.w;
        }
        __syncthreads();
    }

    float4 bias = *reinterpret_cast<const float4*>(
        &g_scratch[BSUM_OFF + dir * 2048 + gcol0 + tx * 4]);
    int b = rowBase >> 7;
#pragma unroll
    for (int i = 0; i < 8; i++) {
        int rw = ty * 8 + i;
        int lo = dir ? (127 - rw) : rw;
        float4 v = make_float4(acc[i][0] + bias.x, acc[i][1] + bias.y,
                               acc[i][2] + bias.z, acc[i][3] + bias.w);
        *reinterpret_cast<float4*>(
            &g_scratch[XP_OFF + (size_t)dir * 4194304
                       + (size_t)(b * 128 + lo) * 2048 + gcol0 + tx * 4]) = v;
    }
}

// ---------------- generic NT SGEMM (small selection GEMMs) -------------------
__global__ __launch_bounds__(256) void sgemm_nt(
    int aOff, int lda, const float* __restrict__ Bm, int ldb,
    int cOff, int N, int K,
    const float* __restrict__ biasExt, int relu)
{
    __shared__ float As[64][33];
    __shared__ float Bs[64][33];
    int tid = threadIdx.x;
    int tx = tid & 15, ty = tid >> 4;
    int rowBase = blockIdx.y * 64;
    int colBase = blockIdx.x * 64;
    const float* A = g_scratch + aOff;

    float acc[4][4];
#pragma unroll
    for (int i = 0; i < 4; i++)
#pragma unroll
        for (int j = 0; j < 4; j++) acc[i][j] = 0.f;

    for (int k0 = 0; k0 < K; k0 += 32) {
#pragma unroll
        for (int i = 0; i < 8; i++) {
            int p = tid + i * 256;
            int r = p >> 5, c = p & 31;
            int gk = k0 + c;
            As[r][c] = (gk < K) ? A[(size_t)(rowBase + r) * lda + gk] : 0.f;
            Bs[r][c] = (gk < K) ? Bm[(size_t)(colBase + r) * ldb + gk] : 0.f;
        }
        __syncthreads();
#pragma unroll
        for (int k = 0; k < 32; k++) {
            float a0 = As[ty * 4 + 0][k], a1 = As[ty * 4 + 1][k];
            float a2 = As[ty * 4 + 2][k], a3 = As[ty * 4 + 3][k];
            float b0 = Bs[tx * 4 + 0][k], b1 = Bs[tx * 4 + 1][k];
            float b2 = Bs[tx * 4 + 2][k], b3 = Bs[tx * 4 + 3][k];
            acc[0][0] += a0 * b0; acc[0][1] += a0 * b1; acc[0][2] += a0 * b2; acc[0][3] += a0 * b3;
            acc[1][0] += a1 * b0; acc[1][1] += a1 * b1; acc[1][2] += a1 * b2; acc[1][3] += a1 * b3;
            acc[2][0] += a2 * b0; acc[2][1] += a2 * b1; acc[2][2] += a2 * b2; acc[2][3] += a2 * b3;
            acc[3][0] += a3 * b0; acc[3][1] += a3 * b1; acc[3][2] += a3 * b2; acc[3][3] += a3 * b3;
        }
        __syncthreads();
    }

    float* C = g_scratch + cOff;
#pragma unroll
    for (int i = 0; i < 4; i++) {
        int row = rowBase + ty * 4 + i;
#pragma unroll
        for (int jn = 0; jn < 4; jn++) {
            int col = colBase + tx * 4 + jn;
            float v = acc[i][jn];
            if (biasExt) v += biasExt[col];
            if (relu) v = fmaxf(v, 0.f);
            C[(size_t)row * N + col] = v;
        }
    }
}

// ---------------- persistent BiLSTM: all 128 timesteps in one kernel ---------
// (R6 proven version: warp-uniform broadcast h reads, smem partials.)
// Grid: 128 blocks = dir(2) x slice(64). Block owns 8 j's x 4 gates = 32 gate
// rows; W_hh slice lives in registers for the whole kernel. Per step:
// load h_prev[16][512] to smem; matvec in 2 passes of 8 batches (partials
// buffer = 8KB); gate fuse; write h to HS history; software grid barrier.
// smem: 32KB (h) + 8KB (partials) dynamic + 512B static = 40.5KB <= 48KB.
__global__ __launch_bounds__(256, 1) void lstm_persist(
    const float* __restrict__ whhf, const float* __restrict__ whhb)
{
    int bx  = blockIdx.x;
    int dir = bx & 1;
    int s   = bx >> 1;          // 0..63
    int j0  = s * 8;
    const float* whh = dir ? whhb : whhf;

    extern __shared__ float dsh[];
    float4* h4    = (float4*)dsh;          // 2048 float4 = 32KB: h_prev[16][512]
    float*  spart = dsh + 8192;            // [8][256] = 8KB partials
    __shared__ float sc[128];              // cell state for (b, jj)

    int tid = threadIdx.x;
    int row = tid & 31;                    // row within block's 32 gate rows
    int ks  = tid >> 5;                    // k-split 0..7 (64 k each)
    int g   = row >> 3, jj = row & 7;
    int gr  = g * 512 + j0 + jj;           // global gate row [0,2048)

    // preload W slice into registers as f32x2 pairs: W[gr][ks*64 .. ks*64+63]
    unsigned long long wreg[32];
    {
        const ulonglong2* wsrc =
            reinterpret_cast<const ulonglong2*>(whh + (size_t)gr * 512 + ks * 64);
#pragma unroll
        for (int kk = 0; kk < 16; kk++) {
            ulonglong2 w = wsrc[kk];
            wreg[2 * kk] = w.x;
            wreg[2 * kk + 1] = w.y;
        }
    }
    if (tid < 128) sc[tid] = 0.f;

    for (int t = 0; t < NL; t++) {
        // ---- load h_prev into smem ----
        if (t == 0) {
            float4 z = make_float4(0.f, 0.f, 0.f, 0.f);
            for (int p = tid; p < 2048; p += 256) h4[p] = z;
        } else {
            const float4* hsrc = reinterpret_cast<const float4*>(
                g_scratch + HS_OFF + (size_t)dir * 1048576 + (size_t)(t - 1) * 8192);
            for (int p = tid; p < 2048; p += 256) h4[p] = hsrc[p];
        }
        __syncthreads();

        // ---- matvec + fuse in two passes of 8 batches ----
#pragma unroll 1
        for (int g2 = 0; g2 < 2; g2++) {
#pragma unroll 1
            for (int b = 0; b < 8; b++) {
                int bb = g2 * 8 + b;
                const ulonglong2* hb =
                    reinterpret_cast<const ulonglong2*>(h4 + bb * 128 + ks * 16);
                unsigned long long acc2 = 0ull;    // (+0.f, +0.f)
#pragma unroll
                for (int kk = 0; kk < 16; kk++) {
                    ulonglong2 h2 = hb[kk];
                    FMA_F32X2(acc2, wreg[2 * kk], h2.x);
                    FMA_F32X2(acc2, wreg[2 * kk + 1], h2.y);
                }
                float2 af = *reinterpret_cast<float2*>(&acc2);
                spart[b * 256 + tid] = af.x + af.y;
            }
            __syncthreads();

            // gate fuse + cell update: 64 threads = 8 batches x 8 j's
            if (tid < 64) {
                int b = tid >> 3, j2 = tid & 7;
                int bb = g2 * 8 + b;
                float s0 = 0.f, s1 = 0.f, s2 = 0.f, s3 = 0.f;
#pragma unroll
                for (int k2 = 0; k2 < 8; k2++) {
                    const float* pp = spart + b * 256 + k2 * 32 + j2;
                    s0 += pp[0];
                    s1 += pp[8];
                    s2 += pp[16];
                    s3 += pp[24];
                }
                const float* xp = g_scratch + XP_OFF + (size_t)dir * 4194304
                                  + (size_t)(bb * NL + t) * 2048;
                int j = j0 + j2;
                float iv = s0 + xp[j];
                float fv = s1 + xp[512 + j];
                float gv = s2 + xp[1024 + j];
                float ov = s3 + xp[1536 + j];
                float cold = sc[bb * 8 + j2];
                float cnew = sigm(fv) * cold + sigm(iv) * tanhf(gv);
                float hnew = sigm(ov) * tanhf(cnew);
                sc[bb * 8 + j2] = cnew;
                g_scratch[HS_OFF + (size_t)dir * 1048576 + (size_t)t * 8192
                          + (size_t)bb * 512 + j] = hnew;
            }
            __syncthreads();
        }

        // ---- grid barrier (monotonic counters, reset by zero_kernel) ----
        if (tid == 0) {
            __threadfence();
            unsigned a = atomicAdd(&g_arrive, 1u) + 1u;
            unsigned target = (unsigned)(128 * (t + 1));
            if (a == target) {
                atomicExch(&g_release, (unsigned)(t + 1));
            } else {
                while (atomicAdd(&g_release, 0u) < (unsigned)(t + 1)) { }
            }
            __threadfence();
        }
        __syncthreads();
    }
}

// ---------------- oc = concat(0.5*(hf+hb_rev), bio_emb[bio_gold]) ------------
__global__ void oc_kernel(const int* __restrict__ biog, const float* __restrict__ bemb) {
    int idx = blockIdx.x * blockDim.x + threadIdx.x;   // < 2048*576
    int row = idx / 576, k = idx - row * 576;
    float v;
    if (k < 512) {
        int b = row >> 7, ll = row & 127;
        float hf = g_scratch[HS_OFF + (size_t)ll * 8192 + (size_t)b * 512 + k];
        float hb = g_scratch[HS_OFF + 1048576 + (size_t)(NL - 1 - ll) * 8192 + (size_t)b * 512 + k];
        v = 0.5f * (hf + hb);
    } else {
        v = bemb[(size_t)biog[row] * NBIOE + (k - 512)];
    }
    g_scratch[OC_OFF + idx] = v;
}

// ---------------- emission: emi = o @ Ew^T + eb (o = OC[:, :512]) ------------
__global__ void emi_kernel(const float* __restrict__ ew, const float* __restrict__ eb) {
    int idx = blockIdx.x * blockDim.x + threadIdx.x;
    if (idx >= 2048 * NT) return;
    int row = idx / NT, tag = idx - row * NT;
    const float4* o4 = reinterpret_cast<const float4*>(g_scratch + OC_OFF + (size_t)row * 576);
    const float4* w4 = reinterpret_cast<const float4*>(ew + (size_t)tag * 512);
    float s = 0.f;
#pragma unroll 4
    for (int k = 0; k < 128; k++) {
        float4 a = o4[k], b = w4[k];
        s += a.x * b.x + a.y * b.y + a.z * b.z + a.w * b.w;
    }
    g_scratch[EMI_OFF + idx] = s + eb[tag];
}

// ---------------- CRF NLL (tiny; 1 block) ----------------
__global__ void crf_kernel(const int* __restrict__ tokens, const int* __restrict__ tags,
                           const float* __restrict__ trans, const float* __restrict__ startv,
                           const float* __restrict__ endv)
{
    __shared__ float st[81], ss[9], se[9];
    __shared__ float alpha[16][9], nxt[16][9];
    __shared__ float num[16];
    __shared__ int prev[16];
    __shared__ float res[16];
    int tid = threadIdx.x;
    if (tid < 81) st[tid] = trans[tid];
    if (tid < 9) { ss[tid] = startv[tid]; se[tid] = endv[tid]; }
    __syncthreads();
    int b = tid / 9, j = tid - b * 9;
    const float* emi = g_scratch + EMI_OFF;
    if (tid < 144) {
        alpha[b][j] = ss[j] + emi[(size_t)(b * NL) * NT + j];
        if (j == 0) {
            int t0 = tags[b * NL];
            num[b] = ss[t0] + emi[(size_t)(b * NL) * NT + t0];
            prev[b] = t0;
        }
    }
    __syncthreads();
    for (int t = 1; t < NL; t++) {
        int m = 0;
        if (tid < 144) {
            m = (tokens[b * NL + t] != 0);
            float mx = -1e30f;
#pragma unroll
            for (int i = 0; i < 9; i++) mx = fmaxf(mx, alpha[b][i] + st[i * 9 + j]);
            float s = 0.f;
#pragma unroll
            for (int i = 0; i < 9; i++) s += expf(alpha[b][i] + st[i * 9 + j] - mx);
            float nv = mx + logf(s) + emi[(size_t)(b * NL + t) * NT + j];
            nxt[b][j] = m ? nv : alpha[b][j];
        }
        __syncthreads();
        if (tid < 144) {
            alpha[b][j] = nxt[b][j];
            if (j == 0 && m) {
                int tg = tags[b * NL + t];
                num[b] += st[prev[b] * 9 + tg] + emi[(size_t)(b * NL + t) * NT + tg];
                prev[b] = tg;
            }
        }
        __syncthreads();
    }
    if (tid < 16) {
        float nb = num[tid] + se[prev[tid]];
        float mx = -1e30f;
        for (int i2 = 0; i2 < 9; i2++) mx = fmaxf(mx, alpha[tid][i2] + se[i2]);
        float s = 0.f;
        for (int i2 = 0; i2 < 9; i2++) s += expf(alpha[tid][i2] + se[i2] - mx);
        res[tid] = nb - (mx + logf(s));
    }
    __syncthreads();
    if (tid == 0) {
        float tot = 0.f;
        for (int i2 = 0; i2 < 16; i2++) tot += res[i2];
        g_crf_loss = -tot / 16.f;
    }
}

// ---------------- fused selection: uv build + einsum + BCE + masked sum ------
__global__ __launch_bounds__(128) void sel_kernel(const int* __restrict__ gold,
                                                  const float* __restrict__ rel,
                                                  const float* __restrict__ uvb)
{
    __shared__ __align__(16) float srel[NR * NREL];   // 25.6KB
    __shared__ __align__(16) float sv0[NREL], sv1[NREL];
    __shared__ float sred[4];

    int bx = blockIdx.x;
    int b  = bx >> 6;
    int i0 = (bx & 63) << 1;
    int tid = threadIdx.x;

    for (int p = tid; p < NR * NREL; p += 128) srel[p] = rel[p];
    const float* v2 = g_scratch + V2_OFF;
    sv0[tid] = v2[(size_t)(b * NL + i0) * NREL + tid] + uvb[tid];
    sv1[tid] = v2[(size_t)(b * NL + i0 + 1) * NREL + tid] + uvb[tid];
    __syncthreads();

    int j = tid;
    const float4* u1r = reinterpret_cast<const float4*>(g_scratch + U1_OFF + (size_t)(b * NL + j) * NREL);
    const float4* s0_4 = reinterpret_cast<const float4*>(sv0);
    const float4* s1_4 = reinterpret_cast<const float4*>(sv1);
    const float4* rel4 = reinterpret_cast<const float4*>(srel);

    float acc0[NR], acc1[NR];
#pragma unroll
    for (int r = 0; r < NR; r++) { acc0[r] = 0.f; acc1[r] = 0.f; }

#pragma unroll 4
    for (int h4 = 0; h4 < 32; h4++) {
        float4 uu = u1r[h4];
        float4 a = s0_4[h4];
        float4 c = s1_4[h4];
        float x0x = fmaxf(uu.x + a.x, 0.f), x0y = fmaxf(uu.y + a.y, 0.f);
        float x0z = fmaxf(uu.z + a.z, 0.f), x0w = fmaxf(uu.w + a.w, 0.f);
        float x1x = fmaxf(uu.x + c.x, 0.f), x1y = fmaxf(uu.y + c.y, 0.f);
        float x1z = fmaxf(uu.z + c.z, 0.f), x1w = fmaxf(uu.w + c.w, 0.f);
#pragma unroll
        for (int r = 0; r < NR; r++) {
            float4 rv = rel4[r * 32 + h4];
            acc0[r] += x0x * rv.x + x0y * rv.y + x0z * rv.z + x0w * rv.w;
            acc1[r] += x1x * rv.x + x1y * rv.y + x1z * rv.z + x1w * rv.w;
        }
    }

    float mi0 = g_scratch[MASKF_OFF + b * NL + i0];
    float mi1 = g_scratch[MASKF_OFF + b * NL + i0 + 1];
    float mj  = g_scratch[MASKF_OFF + b * NL + j];
    const int* g0 = gold + (size_t)(b * NL + i0) * NR * NL + j;
    const int* g1 = gold + (size_t)(b * NL + i0 + 1) * NR * NL + j;
    float s0 = 0.f, s1 = 0.f;
#pragma unroll
    for (int r = 0; r < NR; r++) {
        float x = acc0[r];
        float gg = (float)g0[(size_t)r * NL];
        s0 += fmaxf(x, 0.f) - x * gg + log1pf(expf(-fabsf(x)));
        x = acc1[r];
        gg = (float)g1[(size_t)r * NL];
        s1 += fmaxf(x, 0.f) - x * gg + log1pf(expf(-fabsf(x)));
    }
    float part = mj * (mi0 * s0 + mi1 * s1);

#pragma unroll
    for (int off = 16; off; off >>= 1) part += __shfl_down_sync(0xFFFFFFFFu, part, off);
    if ((tid & 31) == 0) sred[tid >> 5] = part;
    __syncthreads();
    if (tid == 0) {
        double tot = (double)sred[0] + (double)sred[1] + (double)sred[2] + (double)sred[3];
        atomicAdd(&g_sel_sum, tot);
    }
}

// ---------------- final scalar ----------------
__global__ void final_kernel(float* out) {
    out[0] = g_crf_loss + (float)(g_sel_sum / (double)g_mask_count);
}

// ============================================================================
extern "C" void kernel_launch(void* const* d_in, const int* in_sizes, int n_in,
                              void* d_out, int out_size)
{
    const int*   tokens     = (const int*)d_in[0];
    const int*   bio_gold   = (const int*)d_in[1];
    const int*   sel_gold   = (const int*)d_in[2];
    // d_in[3] = is_train (unused)
    const float* word_emb   = (const float*)d_in[4];
    const float* rel_emb    = (const float*)d_in[5];
    const float* bio_emb    = (const float*)d_in[6];
    const float* w_ih_f     = (const float*)d_in[7];
    const float* w_hh_f     = (const float*)d_in[8];
    const float* b_ih_f     = (const float*)d_in[9];
    const float* b_hh_f     = (const float*)d_in[10];
    const float* w_ih_b     = (const float*)d_in[11];
    const float* w_hh_b     = (const float*)d_in[12];
    const float* b_ih_b     = (const float*)d_in[13];
    const float* b_hh_b     = (const float*)d_in[14];
    const float* emission_w = (const float*)d_in[15];
    const float* emission_b = (const float*)d_in[16];
    const float* sel_u_w    = (const float*)d_in[17];
    const float* sel_u_b    = (const float*)d_in[18];
    const float* sel_v_w    = (const float*)d_in[19];
    const float* sel_v_b    = (const float*)d_in[20];
    const float* sel_uv_w   = (const float*)d_in[21];
    const float* sel_uv_b   = (const float*)d_in[22];
    const float* crf_trans  = (const float*)d_in[23];
    const float* crf_start  = (const float*)d_in[24];
    const float* crf_end    = (const float*)d_in[25];

    zero_kernel<<<1, 1>>>();
    embed_kernel<<<2400, 256>>>(tokens, word_emb);
    bsum_kernel<<<16, 256>>>(b_ih_f, b_hh_f, b_ih_b, b_hh_b);

    // fused input projection for both directions (reads emb once)
    xproj_gemm<<<dim3(64, 16), 256>>>(w_ih_f, w_ih_b);

    // persistent BiLSTM over all timesteps (40KB dynamic smem)
    lstm_persist<<<128, 256, 40960>>>(w_hh_f, w_hh_b);

    oc_kernel<<<4608, 256>>>(bio_gold, bio_emb);
    emi_kernel<<<(2048 * NT + 127) / 128, 128>>>(emission_w, emission_b);
    crf_kernel<<<1, 160>>>(tokens, bio_gold, crf_trans, crf_start, crf_end);

    // u = relu(oc @ sel_u_w^T + b), v likewise (A rows stride 576 in OC)
    sgemm_nt<<<dim3(2, 32), 256>>>(OC_OFF, 576, sel_u_w, 576,
                                   U_OFF, NREL, 576, sel_u_b, 1);
    sgemm_nt<<<dim3(2, 32), 256>>>(OC_OFF, 576, sel_v_w, 576,
                                   V_OFF, NREL, 576, sel_v_b, 1);
    // u1 = u @ w1^T, v2 = v @ w2^T  (w1/w2 = halves of sel_uv_w, ldb=256)
    sgemm_nt<<<dim3(2, 32), 256>>>(U_OFF, NREL, sel_uv_w, 2 * NREL,
                                   U1_OFF, NREL, NREL, nullptr, 0);
    sgemm_nt<<<dim3(2, 32), 256>>>(V_OFF, NREL, sel_uv_w + NREL, 2 * NREL,
                                   V2_OFF, NREL, NREL, nullptr, 0);

    sel_kernel<<<1024, 128>>>(sel_gold, rel_emb, sel_uv_b);
    final_kernel<<<1, 1>>>((float*)d_out);
}

// round 9
// speedup vs baseline: 3.9584x; 1.0429x over previous
#include <cuda_runtime.h>
#include <cstdint>

// Problem constants
#define NB   16
#define NL   128
#define NE   300
#define NH   512
#define NT   9
#define NBIOE 64
#define NREL 128
#define NR   50

// ---------------- scratch layout (floats) ----------------
#define EMB_OFF    0            // 2048*300
#define BSUM_OFF   1228800      // 2*2048
#define XP_OFF     1232896      // 2 * 2048*2048
#define HS_OFF     9621504      // 2 * 128*16*512
#define EMI_OFF    12783616     // 2048*9
#define OC_OFF     12802048     // 2048*576
#define U_OFF      13981696     // 2048*128
#define V_OFF      14243840     // 2048*128
#define U1_OFF     14505984     // 2048*128
#define V2_OFF     14768128     // 2048*128
#define MASKF_OFF  15030272     // 2048
#define SCRATCH_SZ 15032320

__device__ __align__(16) float g_scratch[SCRATCH_SZ];
__device__ double g_sel_sum;
__device__ int    g_mask_count;
__device__ float  g_crf_loss;
__device__ unsigned g_arrive2[2];
__device__ unsigned g_release2[2];

__device__ __forceinline__ float sigm(float x) { return 1.f / (1.f + expf(-x)); }

#define FMA_F32X2(d, a, b) \
    asm("fma.rn.f32x2 %0, %1, %2, %0;" : "+l"(d) : "l"(a), "l"(b))

// ---------------- zero accumulators ----------------
__global__ void zero_kernel() {
    g_sel_sum = 0.0;
    g_mask_count = 0;
    g_crf_loss = 0.f;
    g_arrive2[0] = 0u; g_arrive2[1] = 0u;
    g_release2[0] = 0u; g_release2[1] = 0u;
}

// ---------------- embedding gather + mask ----------------
__global__ void embed_kernel(const int* __restrict__ tokens,
                             const float* __restrict__ wemb) {
    int idx = blockIdx.x * blockDim.x + threadIdx.x;   // < 2048*300
    int bl = idx / NE;
    int e  = idx - bl * NE;
    int tok = tokens[bl];
    g_scratch[EMB_OFF + idx] = wemb[(size_t)tok * NE + e];
    if (e == 0) {
        g_scratch[MASKF_OFF + bl] = (tok != 0) ? 1.f : 0.f;
        if (tok != 0) atomicAdd(&g_mask_count, 1);
    }
}

// ---------------- combined biases ----------------
__global__ void bsum_kernel(const float* bif, const float* bhf,
                            const float* bib, const float* bhb) {
    int idx = blockIdx.x * blockDim.x + threadIdx.x;   // < 4096
    int d = idx >> 11, g = idx & 2047;
    g_scratch[BSUM_OFF + idx] = d ? (bib[g] + bhb[g]) : (bif[g] + bhf[g]);
}

// ---------------- fused xproj GEMM (proven: 125us) ---------------------------
#define KTILE 16
__global__ __launch_bounds__(256) void xproj_gemm(
    const float* __restrict__ wf, const float* __restrict__ wb)
{
    __shared__ float As[KTILE][132];
    __shared__ float Bs[KTILE][68];
    int tid = threadIdx.x;
    int tx = tid & 15, ty = tid >> 4;
    int rowBase = blockIdx.y * 128;
    int colBase = blockIdx.x * 64;
    int dir = colBase >> 11;
    const float* Bmat = dir ? wb : wf;
    int gcol0 = colBase & 2047;

    float acc[8][4];
#pragma unroll
    for (int i = 0; i < 8; i++)
#pragma unroll
        for (int j = 0; j < 4; j++) acc[i][j] = 0.f;

    for (int k0 = 0; k0 < NE; k0 += KTILE) {
#pragma unroll
        for (int i = 0; i < 2; i++) {
            int f = tid + i * 256;
            int r = f >> 2, kq = f & 3;
            int gk = k0 + kq * 4;
            float4 v = make_float4(0.f, 0.f, 0.f, 0.f);
            if (gk < NE)
                v = *reinterpret_cast<const float4*>(
                        &g_scratch[EMB_OFF + (size_t)(rowBase + r) * NE + gk]);
            As[kq * 4 + 0][r] = v.x;
            As[kq * 4 + 1][r] = v.y;
            As[kq * 4 + 2][r] = v.z;
            As[kq * 4 + 3][r] = v.w;
        }
        {
            int n = tid >> 2, kq = tid & 3;
            int gk = k0 + kq * 4;
            float4 v = make_float4(0.f, 0.f, 0.f, 0.f);
            if (gk < NE)
                v = *reinterpret_cast<const float4*>(
                        &Bmat[(size_t)(gcol0 + n) * NE + gk]);
            Bs[kq * 4 + 0][n] = v.x;
            Bs[kq * 4 + 1][n] = v.y;
            Bs[kq * 4 + 2][n] = v.z;
            Bs[kq * 4 + 3][n] = v.w;
        }
        __syncthreads();
#pragma unroll
        for (int k = 0; k < KTILE; k++) {
            float4 a0 = *reinterpret_cast<const float4*>(&As[k][ty * 8]);
            float4 a1 = *reinterpret_cast<const float4*>(&As[k][ty * 8 + 4]);
            float4 bq = *reinterpret_cast<const float4*>(&Bs[k][tx * 4]);
            acc[0][0] += a0.x * bq.x; acc[0][1] += a0.x * bq.y; acc[0][2] += a0.x * bq.z; acc[0][3] += a0.x * bq.w;
            acc[1][0] += a0.y * bq.x; acc[1][1] += a0.y * bq.y; acc[1][2] += a0.y * bq.z; acc[1][3] += a0.y * bq.w;
            acc[2][0] += a0.z * bq.x; acc[2][1] += a0.z * bq.y; acc[2][2] += a0.z * bq.z; acc[2][3] += a0.z * bq.w;
            acc[3][0] += a0.w * bq.x; acc[3][1] += a0.w * bq.y; acc[3][2] += a0.w * bq.z; acc[3][3] += a0.w * bq.w;
            acc[4][0] += a1.x * bq.x; acc[4][1] += a1.x * bq.y; acc[4][2] += a1.x * bq.z; acc[4][3] += a1.x * bq.w;
            acc[5][0] += a1.y * bq.x; acc[5][1] += a1.y * bq.y; acc[5][2] += a1.y * bq.z; acc[5][3] += a1.y * bq.w;
            acc[6][0] += a1.z * bq.x; acc[6][1] += a1.z * bq.y; acc[6][2] += a1.z * bq.z; acc[6][3] += a1.z * bq.w;
            acc[7][0] += a1.w * bq.x; acc[7][1] += a1.w * bq.y; acc[7][2] += a1.w * bq.z; acc[7][3] += a1.w * bq.w;
        }
        __syncthreads();
    }

    float4 bias = *reinterpret_cast<const float4*>(
        &g_scratch[BSUM_OFF + dir * 2048 + gcol0 + tx * 4]);
    int b = rowBase >> 7;
#pragma unroll
    for (int i = 0; i < 8; i++) {
        int rw = ty * 8 + i;
        int lo = dir ? (127 - rw) : rw;
        float4 v = make_float4(acc[i][0] + bias.x, acc[i][1] + bias.y,
                               acc[i][2] + bias.z, acc[i][3] + bias.w);
        *reinterpret_cast<float4*>(
            &g_scratch[XP_OFF + (size_t)dir * 4194304
                       + (size_t)(b * 128 + lo) * 2048 + gcol0 + tx * 4]) = v;
    }
}

// ---------------- dual NT SGEMM: blockIdx.z picks (A,B,C,bias) set -----------
__global__ __launch_bounds__(256) void sgemm_nt2(
    int a0, int a1, int lda,
    const float* __restrict__ B0, const float* __restrict__ B1, int ldb,
    int c0, int c1, int N, int K,
    const float* __restrict__ bias0, const float* __restrict__ bias1, int relu)
{
    __shared__ float As[64][33];
    __shared__ float Bs[64][33];
    int z = blockIdx.z;
    int aOff = z ? a1 : a0;
    int cOff = z ? c1 : c0;
    const float* Bm = z ? B1 : B0;
    const float* biasExt = z ? bias1 : bias0;

    int tid = threadIdx.x;
    int tx = tid & 15, ty = tid >> 4;
    int rowBase = blockIdx.y * 64;
    int colBase = blockIdx.x * 64;
    const float* A = g_scratch + aOff;

    float acc[4][4];
#pragma unroll
    for (int i = 0; i < 4; i++)
#pragma unroll
        for (int j = 0; j < 4; j++) acc[i][j] = 0.f;

    for (int k0 = 0; k0 < K; k0 += 32) {
#pragma unroll
        for (int i = 0; i < 8; i++) {
            int p = tid + i * 256;
            int r = p >> 5, c = p & 31;
            int gk = k0 + c;
            As[r][c] = (gk < K) ? A[(size_t)(rowBase + r) * lda + gk] : 0.f;
            Bs[r][c] = (gk < K) ? Bm[(size_t)(colBase + r) * ldb + gk] : 0.f;
        }
        __syncthreads();
#pragma unroll
        for (int k = 0; k < 32; k++) {
            float a0v = As[ty * 4 + 0][k], a1v = As[ty * 4 + 1][k];
            float a2v = As[ty * 4 + 2][k], a3v = As[ty * 4 + 3][k];
            float b0 = Bs[tx * 4 + 0][k], b1 = Bs[tx * 4 + 1][k];
            float b2 = Bs[tx * 4 + 2][k], b3 = Bs[tx * 4 + 3][k];
            acc[0][0] += a0v * b0; acc[0][1] += a0v * b1; acc[0][2] += a0v * b2; acc[0][3] += a0v * b3;
            acc[1][0] += a1v * b0; acc[1][1] += a1v * b1; acc[1][2] += a1v * b2; acc[1][3] += a1v * b3;
            acc[2][0] += a2v * b0; acc[2][1] += a2v * b1; acc[2][2] += a2v * b2; acc[2][3] += a2v * b3;
            acc[3][0] += a3v * b0; acc[3][1] += a3v * b1; acc[3][2] += a3v * b2; acc[3][3] += a3v * b3;
        }
        __syncthreads();
    }

    float* C = g_scratch + cOff;
#pragma unroll
    for (int i = 0; i < 4; i++) {
        int row = rowBase + ty * 4 + i;
#pragma unroll
        for (int jn = 0; jn < 4; jn++) {
            int col = colBase + tx * 4 + jn;
            float v = acc[i][jn];
            if (biasExt) v += biasExt[col];
            if (relu) v = fmaxf(v, 0.f);
            C[(size_t)row * N + col] = v;
        }
    }
}

// ---------------- persistent BiLSTM ------------------------------------------
// R6-proven data path (broadcast h reads, 2-pass smem partials) with:
//  * per-direction barrier (64 blocks each), ld.acquire polling (no RMW poll)
//  * xp prefetched into regs before the barrier wait
//  * cell state in registers (fuse thread owns same (bb,jj) every step)
// smem: 32KB (h) + 8KB (partials) dynamic = 40KB, no static.
__global__ __launch_bounds__(256, 1) void lstm_persist(
    const float* __restrict__ whhf, const float* __restrict__ whhb)
{
    int bx  = blockIdx.x;
    int dir = bx & 1;
    int s   = bx >> 1;          // 0..63
    int j0  = s * 8;
    const float* whh = dir ? whhb : whhf;

    extern __shared__ float dsh[];
    float4* h4    = (float4*)dsh;          // 2048 float4 = 32KB: h_prev[16][512]
    float*  spart = dsh + 8192;            // [8][256] = 8KB partials

    int tid = threadIdx.x;
    int row = tid & 31;                    // row within block's 32 gate rows
    int ks  = tid >> 5;                    // k-split 0..7 (64 k each)
    int g   = row >> 3, jj = row & 7;
    int gr  = g * 512 + j0 + jj;           // global gate row [0,2048)

    // preload W slice into registers as f32x2 pairs
    unsigned long long wreg[32];
    {
        const ulonglong2* wsrc =
            reinterpret_cast<const ulonglong2*>(whh + (size_t)gr * 512 + ks * 64);
#pragma unroll
        for (int kk = 0; kk < 16; kk++) {
            ulonglong2 w = wsrc[kk];
            wreg[2 * kk] = w.x;
            wreg[2 * kk + 1] = w.y;
        }
    }

    // fuse-thread state (tid<64): handles (bb = g2*8 + (tid>>3), jj = tid&7)
    int fb = tid >> 3, fj = tid & 7;
    int fcol = j0 + fj;
    float creg[2] = {0.f, 0.f};
    const float* xpb = g_scratch + XP_OFF + (size_t)dir * 4194304;
    float* hsbase = g_scratch + HS_OFF + (size_t)dir * 1048576;
    float xr[2][4];
    if (tid < 64) {
#pragma unroll
        for (int g2 = 0; g2 < 2; g2++) {
            int bb = g2 * 8 + fb;
            const float* xp = xpb + (size_t)(bb * NL) * 2048;
            xr[g2][0] = xp[fcol];
            xr[g2][1] = xp[512 + fcol];
            xr[g2][2] = xp[1024 + fcol];
            xr[g2][3] = xp[1536 + fcol];
        }
    }

    unsigned* arr = &g_arrive2[dir];
    unsigned* rel = &g_release2[dir];

    for (int t = 0; t < NL; t++) {
        // ---- load h_prev into smem ----
        if (t == 0) {
            float4 z = make_float4(0.f, 0.f, 0.f, 0.f);
            for (int p = tid; p < 2048; p += 256) h4[p] = z;
        } else {
            const float4* hsrc = reinterpret_cast<const float4*>(
                hsbase + (size_t)(t - 1) * 8192);
            for (int p = tid; p < 2048; p += 256) h4[p] = hsrc[p];
        }
        __syncthreads();

        // ---- matvec + fuse in two passes of 8 batches ----
#pragma unroll 1
        for (int g2 = 0; g2 < 2; g2++) {
#pragma unroll 1
            for (int b = 0; b < 8; b++) {
                int bb = g2 * 8 + b;
                const ulonglong2* hb =
                    reinterpret_cast<const ulonglong2*>(h4 + bb * 128 + ks * 16);
                unsigned long long acc2 = 0ull;
#pragma unroll
                for (int kk = 0; kk < 16; kk++) {
                    ulonglong2 h2 = hb[kk];
                    FMA_F32X2(acc2, wreg[2 * kk], h2.x);
                    FMA_F32X2(acc2, wreg[2 * kk + 1], h2.y);
                }
                float2 af = *reinterpret_cast<float2*>(&acc2);
                spart[b * 256 + tid] = af.x + af.y;
            }
            __syncthreads();

            if (tid < 64) {
                int bb = g2 * 8 + fb;
                float s0 = 0.f, s1 = 0.f, s2 = 0.f, s3 = 0.f;
#pragma unroll
                for (int k2 = 0; k2 < 8; k2++) {
                    const float* pp = spart + fb * 256 + k2 * 32 + fj;
                    s0 += pp[0];
                    s1 += pp[8];
                    s2 += pp[16];
                    s3 += pp[24];
                }
                float iv = s0 + xr[g2][0];
                float fv = s1 + xr[g2][1];
                float gv = s2 + xr[g2][2];
                float ov = s3 + xr[g2][3];
                float cnew = sigm(fv) * creg[g2] + sigm(iv) * tanhf(gv);
                float hnew = sigm(ov) * tanhf(cnew);
                creg[g2] = cnew;
                hsbase[(size_t)t * 8192 + (size_t)bb * 512 + fcol] = hnew;
                if (t + 1 < NL) {   // prefetch next step's xp (hidden by barrier)
                    const float* xp = xpb + (size_t)(bb * NL + t + 1) * 2048;
                    xr[g2][0] = xp[fcol];
                    xr[g2][1] = xp[512 + fcol];
                    xr[g2][2] = xp[1024 + fcol];
                    xr[g2][3] = xp[1536 + fcol];
                }
            }
            __syncthreads();
        }

        // ---- per-direction grid barrier: RMW arrive, LOAD-acquire poll ----
        if (tid == 0) {
            __threadfence();
            unsigned a = atomicAdd(arr, 1u) + 1u;
            if (a == 64u * (unsigned)(t + 1)) {
                asm volatile("fence.acq_rel.gpu;" ::: "memory");
                asm volatile("st.release.gpu.u32 [%0], %1;"
                             :: "l"(rel), "r"(t + 1) : "memory");
            } else {
                unsigned r;
                do {
                    asm volatile("ld.acquire.gpu.u32 %0, [%1];"
                                 : "=r"(r) : "l"(rel) : "memory");
                } while (r < (unsigned)(t + 1));
            }
            __threadfence();
        }
        __syncthreads();
    }
}

// ---------------- oc = concat(0.5*(hf+hb_rev), bio_emb[bio_gold]) ------------
__global__ void oc_kernel(const int* __restrict__ biog, const float* __restrict__ bemb) {
    int idx = blockIdx.x * blockDim.x + threadIdx.x;   // < 2048*576
    int row = idx / 576, k = idx - row * 576;
    float v;
    if (k < 512) {
        int b = row >> 7, ll = row & 127;
        float hf = g_scratch[HS_OFF + (size_t)ll * 8192 + (size_t)b * 512 + k];
        float hb = g_scratch[HS_OFF + 1048576 + (size_t)(NL - 1 - ll) * 8192 + (size_t)b * 512 + k];
        v = 0.5f * (hf + hb);
    } else {
        v = bemb[(size_t)biog[row] * NBIOE + (k - 512)];
    }
    g_scratch[OC_OFF + idx] = v;
}

// ---------------- emission: emi = o @ Ew^T + eb (o = OC[:, :512]) ------------
__global__ void emi_kernel(const float* __restrict__ ew, const float* __restrict__ eb) {
    int idx = blockIdx.x * blockDim.x + threadIdx.x;
    if (idx >= 2048 * NT) return;
    int row = idx / NT, tag = idx - row * NT;
    const float4* o4 = reinterpret_cast<const float4*>(g_scratch + OC_OFF + (size_t)row * 576);
    const float4* w4 = reinterpret_cast<const float4*>(ew + (size_t)tag * 512);
    float s = 0.f;
#pragma unroll 4
    for (int k = 0; k < 128; k++) {
        float4 a = o4[k], b = w4[k];
        s += a.x * b.x + a.y * b.y + a.z * b.z + a.w * b.w;
    }
    g_scratch[EMI_OFF + idx] = s + eb[tag];
}

// ---------------- fused selection + CRF (crf = block 1024, hidden under sel) -
__global__ __launch_bounds__(160) void sel_crf_kernel(
    const int* __restrict__ gold, const float* __restrict__ rel,
    const float* __restrict__ uvb,
    const int* __restrict__ tokens, const int* __restrict__ tags,
    const float* __restrict__ trans, const float* __restrict__ startv,
    const float* __restrict__ endv)
{
    int tid = threadIdx.x;

    if (blockIdx.x >= 1024) {
        // ---------------- CRF path (one block) ----------------
        __shared__ float st[81], ss[9], se[9];
        __shared__ float alpha[16][9], nxt[16][9];
        __shared__ float num[16];
        __shared__ int prev[16];
        __shared__ float res[16];
        if (tid < 81) st[tid] = trans[tid];
        if (tid < 9) { ss[tid] = startv[tid]; se[tid] = endv[tid]; }
        __syncthreads();
        int b = tid / 9, j = tid - b * 9;
        const float* emi = g_scratch + EMI_OFF;
        if (tid < 144) {
            alpha[b][j] = ss[j] + emi[(size_t)(b * NL) * NT + j];
            if (j == 0) {
                int t0 = tags[b * NL];
                num[b] = ss[t0] + emi[(size_t)(b * NL) * NT + t0];
                prev[b] = t0;
            }
        }
        __syncthreads();
        for (int t = 1; t < NL; t++) {
            int m = 0;
            if (tid < 144) {
                m = (tokens[b * NL + t] != 0);
                float mx = -1e30f;
#pragma unroll
                for (int i = 0; i < 9; i++) mx = fmaxf(mx, alpha[b][i] + st[i * 9 + j]);
                float sv = 0.f;
#pragma unroll
                for (int i = 0; i < 9; i++) sv += expf(alpha[b][i] + st[i * 9 + j] - mx);
                float nv = mx + logf(sv) + emi[(size_t)(b * NL + t) * NT + j];
                nxt[b][j] = m ? nv : alpha[b][j];
            }
            __syncthreads();
            if (tid < 144) {
                alpha[b][j] = nxt[b][j];
                if (j == 0 && m) {
                    int tg = tags[b * NL + t];
                    num[b] += st[prev[b] * 9 + tg] + emi[(size_t)(b * NL + t) * NT + tg];
                    prev[b] = tg;
                }
            }
            __syncthreads();
        }
        if (tid < 16) {
            float nb = num[tid] + se[prev[tid]];
            float mx = -1e30f;
            for (int i2 = 0; i2 < 9; i2++) mx = fmaxf(mx, alpha[tid][i2] + se[i2]);
            float sv = 0.f;
            for (int i2 = 0; i2 < 9; i2++) sv += expf(alpha[tid][i2] + se[i2] - mx);
            res[tid] = nb - (mx + logf(sv));
        }
        __syncthreads();
        if (tid == 0) {
            float tot = 0.f;
            for (int i2 = 0; i2 < 16; i2++) tot += res[i2];
            g_crf_loss = -tot / 16.f;
        }
        return;
    }

    // ---------------- selection path ----------------
    __shared__ __align__(16) float srel[NR * NREL];   // 25.6KB
    __shared__ __align__(16) float sv0[NREL], sv1[NREL];
    __shared__ float sred[4];

    int bx = blockIdx.x;
    int b  = bx >> 6;
    int i0 = (bx & 63) << 1;

    for (int p = tid; p < NR * NREL; p += 160) srel[p] = rel[p];
    if (tid < 128) {
        const float* v2 = g_scratch + V2_OFF;
        sv0[tid] = v2[(size_t)(b * NL + i0) * NREL + tid] + uvb[tid];
        sv1[tid] = v2[(size_t)(b * NL + i0 + 1) * NREL + tid] + uvb[tid];
    }
    __syncthreads();

    if (tid < 128) {
        int j = tid;
        const float4* u1r = reinterpret_cast<const float4*>(g_scratch + U1_OFF + (size_t)(b * NL + j) * NREL);
        const float4* s0_4 = reinterpret_cast<const float4*>(sv0);
        const float4* s1_4 = reinterpret_cast<const float4*>(sv1);
        const float4* rel4 = reinterpret_cast<const float4*>(srel);

        float acc0[NR], acc1[NR];
#pragma unroll
        for (int r = 0; r < NR; r++) { acc0[r] = 0.f; acc1[r] = 0.f; }

#pragma unroll 4
        for (int h4 = 0; h4 < 32; h4++) {
            float4 uu = u1r[h4];
            float4 a = s0_4[h4];
            float4 c = s1_4[h4];
            float x0x = fmaxf(uu.x + a.x, 0.f), x0y = fmaxf(uu.y + a.y, 0.f);
            float x0z = fmaxf(uu.z + a.z, 0.f), x0w = fmaxf(uu.w + a.w, 0.f);
            float x1x = fmaxf(uu.x + c.x, 0.f), x1y = fmaxf(uu.y + c.y, 0.f);
            float x1z = fmaxf(uu.z + c.z, 0.f), x1w = fmaxf(uu.w + c.w, 0.f);
#pragma unroll
            for (int r = 0; r < NR; r++) {
                float4 rv = rel4[r * 32 + h4];
                acc0[r] += x0x * rv.x + x0y * rv.y + x0z * rv.z + x0w * rv.w;
                acc1[r] += x1x * rv.x + x1y * rv.y + x1z * rv.z + x1w * rv.w;
            }
        }

        float mi0 = g_scratch[MASKF_OFF + b * NL + i0];
        float mi1 = g_scratch[MASKF_OFF + b * NL + i0 + 1];
        float mj  = g_scratch[MASKF_OFF + b * NL + j];
        const int* g0 = gold + (size_t)(b * NL + i0) * NR * NL + j;
        const int* g1 = gold + (size_t)(b * NL + i0 + 1) * NR * NL + j;
        float s0 = 0.f, s1 = 0.f;
#pragma unroll
        for (int r = 0; r < NR; r++) {
            float x = acc0[r];
            float gg = (float)g0[(size_t)r * NL];
            s0 += fmaxf(x, 0.f) - x * gg + log1pf(expf(-fabsf(x)));
            x = acc1[r];
            gg = (float)g1[(size_t)r * NL];
            s1 += fmaxf(x, 0.f) - x * gg + log1pf(expf(-fabsf(x)));
        }
        float part = mj * (mi0 * s0 + mi1 * s1);

#pragma unroll
        for (int off = 16; off; off >>= 1) part += __shfl_down_sync(0xFFFFFFFFu, part, off);
        if ((tid & 31) == 0) sred[tid >> 5] = part;
    }
    __syncthreads();
    if (tid == 0) {
        double tot = (double)sred[0] + (double)sred[1] + (double)sred[2] + (double)sred[3];
        atomicAdd(&g_sel_sum, tot);
    }
}

// ---------------- final scalar ----------------
__global__ void final_kernel(float* out) {
    out[0] = g_crf_loss + (float)(g_sel_sum / (double)g_mask_count);
}

// ============================================================================
extern "C" void kernel_launch(void* const* d_in, const int* in_sizes, int n_in,
                              void* d_out, int out_size)
{
    const int*   tokens     = (const int*)d_in[0];
    const int*   bio_gold   = (const int*)d_in[1];
    const int*   sel_gold   = (const int*)d_in[2];
    // d_in[3] = is_train (unused)
    const float* word_emb   = (const float*)d_in[4];
    const float* rel_emb    = (const float*)d_in[5];
    const float* bio_emb    = (const float*)d_in[6];
    const float* w_ih_f     = (const float*)d_in[7];
    const float* w_hh_f     = (const float*)d_in[8];
    const float* b_ih_f     = (const float*)d_in[9];
    const float* b_hh_f     = (const float*)d_in[10];
    const float* w_ih_b     = (const float*)d_in[11];
    const float* w_hh_b     = (const float*)d_in[12];
    const float* b_ih_b     = (const float*)d_in[13];
    const float* b_hh_b     = (const float*)d_in[14];
    const float* emission_w = (const float*)d_in[15];
    const float* emission_b = (const float*)d_in[16];
    const float* sel_u_w    = (const float*)d_in[17];
    const float* sel_u_b    = (const float*)d_in[18];
    const float* sel_v_w    = (const float*)d_in[19];
    const float* sel_v_b    = (const float*)d_in[20];
    const float* sel_uv_w   = (const float*)d_in[21];
    const float* sel_uv_b   = (const float*)d_in[22];
    const float* crf_trans  = (const float*)d_in[23];
    const float* crf_start  = (const float*)d_in[24];
    const float* crf_end    = (const float*)d_in[25];

    zero_kernel<<<1, 1>>>();
    embed_kernel<<<2400, 256>>>(tokens, word_emb);
    bsum_kernel<<<16, 256>>>(b_ih_f, b_hh_f, b_ih_b, b_hh_b);

    // fused input projection for both directions
    xproj_gemm<<<dim3(64, 16), 256>>>(w_ih_f, w_ih_b);

    // persistent BiLSTM (40KB dynamic smem)
    lstm_persist<<<128, 256, 40960>>>(w_hh_f, w_hh_b);

    oc_kernel<<<4608, 256>>>(bio_gold, bio_emb);
    emi_kernel<<<(2048 * NT + 127) / 128, 128>>>(emission_w, emission_b);

    // u = relu(oc@u_w^T+b) and v = relu(oc@v_w^T+b) in one launch
    sgemm_nt2<<<dim3(2, 32, 2), 256>>>(OC_OFF, OC_OFF, 576,
                                       sel_u_w, sel_v_w, 576,
                                       U_OFF, V_OFF, NREL, 576,
                                       sel_u_b, sel_v_b, 1);
    // u1 = u@w1^T and v2 = v@w2^T in one launch
    sgemm_nt2<<<dim3(2, 32, 2), 256>>>(U_OFF, V_OFF, NREL,
                                       sel_uv_w, sel_uv_w + NREL, 2 * NREL,
                                       U1_OFF, V2_OFF, NREL, NREL,
                                       nullptr, nullptr, 0);

    // selection loss (1024 blocks) + CRF (block 1024) overlapped
    sel_crf_kernel<<<1025, 160>>>(sel_gold, rel_emb, sel_uv_b,
                                  tokens, bio_gold,
                                  crf_trans, crf_start, crf_end);
    final_kernel<<<1, 1>>>((float*)d_out);
}